// round 1
// baseline (speedup 1.0000x reference)
#include <cuda_runtime.h>

#define NROWS 8192
#define DDIM  512
#define NTRIP 200000

// Scratch (allocation-free rule: __device__ globals)
__device__ float  g_yn[NROWS * DDIM];   // normalized y rows (16 MB)
__device__ float  g_sqx[NROWS];         // row squared-norms of x
__device__ double g_accum;              // loss accumulator

// ---------------------------------------------------------------------------
// prep: per row, compute ||x||^2, normalize y -> g_yn. Block 0 zeroes g_accum.
// 8192 blocks x 128 threads; D/4 = 128 float4 per row -> 1 float4 per thread.
// ---------------------------------------------------------------------------
__global__ void prep_kernel(const float* __restrict__ x,
                            const float* __restrict__ y,
                            const float* __restrict__ norm_s) {
    const int row = blockIdx.x;
    const int tid = threadIdx.x;           // 128 threads
    if (row == 0 && tid == 0) g_accum = 0.0;

    const float4* xr = (const float4*)(x + (size_t)row * DDIM);
    const float4* yr = (const float4*)(y + (size_t)row * DDIM);

    float4 xv = xr[tid];
    float4 yv = yr[tid];
    float sx = xv.x * xv.x + xv.y * xv.y + xv.z * xv.z + xv.w * xv.w;
    float sy = yv.x * yv.x + yv.y * yv.y + yv.z * yv.z + yv.w * yv.w;

    // warp reduce
    #pragma unroll
    for (int off = 16; off; off >>= 1) {
        sx += __shfl_xor_sync(0xFFFFFFFFu, sx, off);
        sy += __shfl_xor_sync(0xFFFFFFFFu, sy, off);
    }
    __shared__ float shx[4], shy[4];
    const int wid = tid >> 5, lane = tid & 31;
    if (lane == 0) { shx[wid] = sx; shy[wid] = sy; }
    __syncthreads();

    float sx_tot = shx[0] + shx[1] + shx[2] + shx[3];
    float sy_tot = shy[0] + shy[1] + shy[2] + shy[3];

    if (tid == 0) g_sqx[row] = sx_tot;

    const float scale = norm_s[0] / sqrtf(sy_tot);
    float4 o;
    o.x = yv.x * scale; o.y = yv.y * scale;
    o.z = yv.z * scale; o.w = yv.w * scale;
    ((float4*)(g_yn + (size_t)row * DDIM))[tid] = o;
}

// ---------------------------------------------------------------------------
// triplet kernel: one warp per triplet. Gathers 6 rows from L2, computes the
// 4 dot products (x_i.x_j, x_i.x_k, yn_i.yn_j, yn_i.yn_k), softplus, reduces.
// ---------------------------------------------------------------------------
__device__ __forceinline__ float softplus_f(float z) {
    return fmaxf(z, 0.0f) + log1pf(expf(-fabsf(z)));
}

__global__ __launch_bounds__(256, 8)
void triplet_kernel(const float* __restrict__ x,
                    const int* __restrict__ trips,
                    const float* __restrict__ norm_s) {
    const int warp = threadIdx.x >> 5;
    const int lane = threadIdx.x & 31;
    const int t = blockIdx.x * 8 + warp;

    float val = 0.0f;
    if (t < NTRIP) {
        const int i = trips[3 * t + 0];
        const int j = trips[3 * t + 1];
        const int k = trips[3 * t + 2];

        const float4* xi = (const float4*)(x    + (size_t)i * DDIM);
        const float4* xj = (const float4*)(x    + (size_t)j * DDIM);
        const float4* xk = (const float4*)(x    + (size_t)k * DDIM);
        const float4* yi = (const float4*)(g_yn + (size_t)i * DDIM);
        const float4* yj = (const float4*)(g_yn + (size_t)j * DDIM);
        const float4* yk = (const float4*)(g_yn + (size_t)k * DDIM);

        float axj = 0.f, axk = 0.f, ayj = 0.f, ayk = 0.f;
        #pragma unroll
        for (int it = 0; it < 4; ++it) {
            const int c = it * 32 + lane;          // 128 float4 per row
            const float4 a = __ldg(&xi[c]);
            const float4 b = __ldg(&xj[c]);
            const float4 d = __ldg(&xk[c]);
            const float4 p = __ldg(&yi[c]);
            const float4 q = __ldg(&yj[c]);
            const float4 r = __ldg(&yk[c]);
            axj += a.x * b.x + a.y * b.y + a.z * b.z + a.w * b.w;
            axk += a.x * d.x + a.y * d.y + a.z * d.z + a.w * d.w;
            ayj += p.x * q.x + p.y * q.y + p.z * q.z + p.w * q.w;
            ayk += p.x * r.x + p.y * r.y + p.z * r.z + p.w * r.w;
        }
        #pragma unroll
        for (int off = 16; off; off >>= 1) {
            axj += __shfl_xor_sync(0xFFFFFFFFu, axj, off);
            axk += __shfl_xor_sync(0xFFFFFFFFu, axk, off);
            ayj += __shfl_xor_sync(0xFFFFFFFFu, ayj, off);
            ayk += __shfl_xor_sync(0xFFFFFFFFu, ayk, off);
        }
        if (lane == 0) {
            const float sqi = g_sqx[i];
            const float sqj = g_sqx[j];
            const float sqk = g_sqx[k];
            // image modality (clamp to 0 like the reference)
            const float dij = fmaxf(sqi + sqj - 2.0f * axj, 0.0f);
            const float dik = fmaxf(sqi + sqk - 2.0f * axk, 0.0f);
            // text modality: ||y_n||^2 == norm_s^2 for every row
            const float s   = norm_s[0];
            const float s2x2 = 2.0f * s * s;
            const float tij = fmaxf(s2x2 - 2.0f * ayj, 0.0f);
            const float tik = fmaxf(s2x2 - 2.0f * ayk, 0.0f);
            val = softplus_f(dij - dik) + softplus_f(tij - tik);
        }
    }

    __shared__ float sh[8];
    if (lane == 0) sh[warp] = val;
    __syncthreads();
    if (threadIdx.x == 0) {
        float s = 0.f;
        #pragma unroll
        for (int w = 0; w < 8; ++w) s += sh[w];
        atomicAdd(&g_accum, (double)s);
    }
}

__global__ void finalize_kernel(float* __restrict__ out) {
    out[0] = (float)(g_accum * (1.0 / (double)NTRIP));
}

// ---------------------------------------------------------------------------
extern "C" void kernel_launch(void* const* d_in, const int* in_sizes, int n_in,
                              void* d_out, int out_size) {
    const float* x      = (const float*)d_in[0];
    const float* y      = (const float*)d_in[1];
    const float* norm_s = (const float*)d_in[2];
    const int*   trips  = (const int*)d_in[3];
    float*       out    = (float*)d_out;

    prep_kernel<<<NROWS, 128>>>(x, y, norm_s);
    triplet_kernel<<<(NTRIP + 7) / 8, 256>>>(x, trips, norm_s);
    finalize_kernel<<<1, 1>>>(out);
}

// round 2
// speedup vs baseline: 1.5065x; 1.5065x over previous
#include <cuda_runtime.h>
#include <cuda_fp16.h>

#define NROWS 8192
#define DDIM  512
#define NTRIP 200000

// Scratch (allocation-free rule: __device__ globals)
__device__ __align__(16) __half g_xh [NROWS * DDIM];  // fp16 x rows (8 MB)
__device__ __align__(16) __half g_ynh[NROWS * DDIM];  // fp16 normalized y rows (8 MB)
__device__ float  g_sqx[NROWS];                       // exact fp32 ||x||^2
__device__ double g_accum;

// ---------------------------------------------------------------------------
// prep: per row, ||x||^2 (fp32 exact), x -> fp16, y normalized -> fp16.
// 8192 blocks x 128 threads; each thread owns one float4 (4 elems).
// ---------------------------------------------------------------------------
__global__ void prep_kernel(const float* __restrict__ x,
                            const float* __restrict__ y,
                            const float* __restrict__ norm_s) {
    const int row = blockIdx.x;
    const int tid = threadIdx.x;           // 128 threads
    if (row == 0 && tid == 0) g_accum = 0.0;

    const float4 xv = ((const float4*)(x + (size_t)row * DDIM))[tid];
    const float4 yv = ((const float4*)(y + (size_t)row * DDIM))[tid];

    float sx = xv.x * xv.x + xv.y * xv.y + xv.z * xv.z + xv.w * xv.w;
    float sy = yv.x * yv.x + yv.y * yv.y + yv.z * yv.z + yv.w * yv.w;

    #pragma unroll
    for (int off = 16; off; off >>= 1) {
        sx += __shfl_xor_sync(0xFFFFFFFFu, sx, off);
        sy += __shfl_xor_sync(0xFFFFFFFFu, sy, off);
    }
    __shared__ float shx[4], shy[4];
    const int wid = tid >> 5, lane = tid & 31;
    if (lane == 0) { shx[wid] = sx; shy[wid] = sy; }
    __syncthreads();

    const float sx_tot = shx[0] + shx[1] + shx[2] + shx[3];
    const float sy_tot = shy[0] + shy[1] + shy[2] + shy[3];
    if (tid == 0) g_sqx[row] = sx_tot;

    // x -> fp16
    {
        __half2 h0 = __floats2half2_rn(xv.x, xv.y);
        __half2 h1 = __floats2half2_rn(xv.z, xv.w);
        uint2 w; w.x = *(unsigned*)&h0; w.y = *(unsigned*)&h1;
        ((uint2*)(g_xh + (size_t)row * DDIM))[tid] = w;
    }
    // y normalized -> fp16
    {
        const float scale = norm_s[0] * rsqrtf(sy_tot);
        __half2 h0 = __floats2half2_rn(yv.x * scale, yv.y * scale);
        __half2 h1 = __floats2half2_rn(yv.z * scale, yv.w * scale);
        uint2 w; w.x = *(unsigned*)&h0; w.y = *(unsigned*)&h1;
        ((uint2*)(g_ynh + (size_t)row * DDIM))[tid] = w;
    }
}

// ---------------------------------------------------------------------------
// triplet kernel: one warp per triplet, fp16 row gathers, fp32 accumulation.
// Per lane: row = 512 halves -> 16 halves/lane -> 2 x 16B loads per row.
// ---------------------------------------------------------------------------
__device__ __forceinline__ float softplus_f(float z) {
    return fmaxf(z, 0.0f) + log1pf(expf(-fabsf(z)));
}

// unpack uint4 (8 halves) into 8 floats
__device__ __forceinline__ void unpack8(const uint4 v, float* f) {
    float2 a = __half22float2(*(const __half2*)&v.x);
    float2 b = __half22float2(*(const __half2*)&v.y);
    float2 c = __half22float2(*(const __half2*)&v.z);
    float2 d = __half22float2(*(const __half2*)&v.w);
    f[0] = a.x; f[1] = a.y; f[2] = b.x; f[3] = b.y;
    f[4] = c.x; f[5] = c.y; f[6] = d.x; f[7] = d.y;
}

__global__ __launch_bounds__(256, 8)
void triplet_kernel(const int* __restrict__ trips,
                    const float* __restrict__ norm_s) {
    const int warp = threadIdx.x >> 5;
    const int lane = threadIdx.x & 31;
    const int t = blockIdx.x * 8 + warp;

    float val = 0.0f;
    if (t < NTRIP) {
        const int i = trips[3 * t + 0];
        const int j = trips[3 * t + 1];
        const int k = trips[3 * t + 2];

        const uint4* xi = (const uint4*)(g_xh  + (size_t)i * DDIM);
        const uint4* xj = (const uint4*)(g_xh  + (size_t)j * DDIM);
        const uint4* xk = (const uint4*)(g_xh  + (size_t)k * DDIM);
        const uint4* yi = (const uint4*)(g_ynh + (size_t)i * DDIM);
        const uint4* yj = (const uint4*)(g_ynh + (size_t)j * DDIM);
        const uint4* yk = (const uint4*)(g_ynh + (size_t)k * DDIM);

        float axj = 0.f, axk = 0.f, ayj = 0.f, ayk = 0.f;
        #pragma unroll
        for (int it = 0; it < 2; ++it) {
            const int c = it * 32 + lane;           // 64 uint4 per row
            const uint4 va = __ldg(&xi[c]);
            const uint4 vb = __ldg(&xj[c]);
            const uint4 vd = __ldg(&xk[c]);
            const uint4 vp = __ldg(&yi[c]);
            const uint4 vq = __ldg(&yj[c]);
            const uint4 vr = __ldg(&yk[c]);
            float a[8], b[8], d[8], p[8], q[8], r[8];
            unpack8(va, a); unpack8(vb, b); unpack8(vd, d);
            unpack8(vp, p); unpack8(vq, q); unpack8(vr, r);
            #pragma unroll
            for (int e = 0; e < 8; ++e) {
                axj = fmaf(a[e], b[e], axj);
                axk = fmaf(a[e], d[e], axk);
                ayj = fmaf(p[e], q[e], ayj);
                ayk = fmaf(p[e], r[e], ayk);
            }
        }
        #pragma unroll
        for (int off = 16; off; off >>= 1) {
            axj += __shfl_xor_sync(0xFFFFFFFFu, axj, off);
            axk += __shfl_xor_sync(0xFFFFFFFFu, axk, off);
            ayj += __shfl_xor_sync(0xFFFFFFFFu, ayj, off);
            ayk += __shfl_xor_sync(0xFFFFFFFFu, ayk, off);
        }
        if (lane == 0) {
            const float sqi = g_sqx[i];
            const float sqj = g_sqx[j];
            const float sqk = g_sqx[k];
            const float dij = fmaxf(sqi + sqj - 2.0f * axj, 0.0f);
            const float dik = fmaxf(sqi + sqk - 2.0f * axk, 0.0f);
            const float s   = norm_s[0];
            const float s2x2 = 2.0f * s * s;   // ||y_n||^2 == norm_s^2 per row
            const float tij = fmaxf(s2x2 - 2.0f * ayj, 0.0f);
            const float tik = fmaxf(s2x2 - 2.0f * ayk, 0.0f);
            val = softplus_f(dij - dik) + softplus_f(tij - tik);
        }
    }

    __shared__ float sh[8];
    if (lane == 0) sh[warp] = val;
    __syncthreads();
    if (threadIdx.x == 0) {
        float s = 0.f;
        #pragma unroll
        for (int w = 0; w < 8; ++w) s += sh[w];
        atomicAdd(&g_accum, (double)s);
    }
}

__global__ void finalize_kernel(float* __restrict__ out) {
    out[0] = (float)(g_accum * (1.0 / (double)NTRIP));
}

// ---------------------------------------------------------------------------
extern "C" void kernel_launch(void* const* d_in, const int* in_sizes, int n_in,
                              void* d_out, int out_size) {
    const float* x      = (const float*)d_in[0];
    const float* y      = (const float*)d_in[1];
    const float* norm_s = (const float*)d_in[2];
    const int*   trips  = (const int*)d_in[3];
    float*       out    = (float*)d_out;

    prep_kernel<<<NROWS, 128>>>(x, y, norm_s);
    triplet_kernel<<<(NTRIP + 7) / 8, 256>>>(trips, norm_s);
    finalize_kernel<<<1, 1>>>(out);
}